// round 5
// baseline (speedup 1.0000x reference)
#include <cuda_runtime.h>
#include <cuda_fp16.h>
#include <math.h>

// Problem constants (CTCLoss_70961449664599): T=2048, B=64, V=512, S=256
#define T_DIM 2048
#define B_DIM 64
#define V_DIM 512
#define S_DIM 256
#define L_DIM (2 * S_DIM + 1)   // 513 extended positions
#define GP2   272               // padded row: cols 0..255 = symbols, 256 = blank
#define NEG2  (-1.0e30f)
#define LOG2E_F 1.4426950408889634f
#define LN2_F   0.6931471805599453f

// Scratch (allocation-free rule: __device__ globals). +2 rows of padding so the
// depth-2 prefetch can read past T-1 without clamping.
__device__ __half g_G[(size_t)(T_DIM + 2) * B_DIM * GP2];
__device__ float  g_partial[B_DIM];

__device__ __forceinline__ float ex2f_(float x) {
    float y; asm("ex2.approx.f32 %0, %1;" : "=f"(y) : "f"(x)); return y;
}
__device__ __forceinline__ float lg2f_(float x) {
    float y; asm("lg2.approx.f32 %0, %1;" : "=f"(y) : "f"(x)); return y;
}
// 2-term logaddexp2: 2 MUFU
__device__ __forceinline__ float lse2_(float a, float b) {
    const float m = fmaxf(a, b);
    const float d = -fabsf(a - b);
    return m + lg2f_(1.0f + ex2f_(d));
}

// ---------------------------------------------------------------------------
// Phase 1: per (t,b) row -> log2-sum-exp; gathered log2-probs in fp16
//   col j (j<256) = symbol targets[b][j] (ext position 2j+1), col 256 = blank
// Grid: (B, T/8), block: 256 threads (8 warps, 1 warp per t-row)
// ---------------------------------------------------------------------------
__global__ __launch_bounds__(256) void ctc_phase1(
    const float* __restrict__ x, const int* __restrict__ targets)
{
    __shared__ float sh_row[8][V_DIM];
    __shared__ int   sh_tgt[S_DIM];

    const int b    = blockIdx.x;
    const int tid  = threadIdx.x;
    const int w    = tid >> 5;
    const int lane = tid & 31;

    sh_tgt[tid] = targets[b * S_DIM + tid];
    __syncthreads();

    const int t = blockIdx.y * 8 + w;
    const float4* row = (const float4*)(x + ((size_t)t * B_DIM + b) * V_DIM);

    float s = 0.0f;
    float4* shv = (float4*)sh_row[w];
#pragma unroll
    for (int k = 0; k < 4; k++) {
        float4 v = row[lane + 32 * k];
        shv[lane + 32 * k] = v;
        s += ex2f_(v.x * LOG2E_F) + ex2f_(v.y * LOG2E_F)
           + ex2f_(v.z * LOG2E_F) + ex2f_(v.w * LOG2E_F);
    }
#pragma unroll
    for (int o = 16; o; o >>= 1) s += __shfl_xor_sync(0xffffffffu, s, o);
    const float lse2v = lg2f_(s);

    __half* gout = g_G + ((size_t)t * B_DIM + b) * GP2;
#pragma unroll
    for (int j = lane; j < 257; j += 32) {
        const int sym = (j < 256) ? sh_tgt[j] : 0;
        gout[j] = __float2half_rn(sh_row[w][sym] * LOG2E_F - lse2v);
    }
}

// ---------------------------------------------------------------------------
// Phase 2: alpha recursion (log2 domain), SMEM double buffer,
// PARITY-SEGREGATED warps:
//   tid   0..256  -> even positions l = 2*tid (blanks, 2-term LSE)
//   tid 257..287  -> idle (warp-alignment padding)
//   tid 288..543  -> odd positions l = 2*(tid-288)+1 (symbols, 3-term LSE)
// Depth-2 rotating prefetch of the fp16 G column (L2-resident).
// One __syncthreads per time step.
// ---------------------------------------------------------------------------
#define NTH 544
__global__ __launch_bounds__(NTH) void ctc_phase2(
    const int* __restrict__ targets,
    const int* __restrict__ in_len,
    const int* __restrict__ tgt_len)
{
    __shared__ float abuf[2][L_DIM + 2];   // [0],[1] permanent NEG2 pads

    const int b   = blockIdx.x;
    const int tid = threadIdx.x;
    const int Lin = in_len[b];             // block-uniform
    const int Lt  = tgt_len[b];

    const bool is_even = (tid < 257);
    const bool act     = is_even | (tid >= 288);
    const int  i       = tid - 288;                       // odd pair index
    const int  l       = is_even ? (2 * tid) : (2 * i + 1);
    const int  j       = is_even ? 256 : i;               // G column

    bool allow2 = false;
    if (!is_even && act) {
        const int curt  = targets[b * S_DIM + i];
        const int prevt = (i > 0) ? targets[b * S_DIM + i - 1] : 0;
        allow2 = (curt != prevt);   // symbols >= 1, so only repeat check
    }

    const size_t stride = (size_t)B_DIM * GP2;
    const __half* gcol = g_G + (size_t)b * GP2 + j;

    // t = 0 init: only positions 0,1 live
    if (tid < 2) { abuf[0][tid] = NEG2; abuf[1][tid] = NEG2; }
    if (act) abuf[0][2 + l] = (l < 2) ? __half2float(__ldg(gcol)) : NEG2;
    __syncthreads();

    // depth-2 rotating prefetch: g0 = G[1], g1 = G[2]
    const __half* gp = gcol + stride;
    float g0 = act ? __half2float(__ldg(gp)) : 0.0f;
    float g1 = act ? __half2float(__ldg(gp + stride)) : 0.0f;
    gp += 3 * stride;                       // next fetch row = t+2 with t=1

    int cur = 0;
    for (int t = 1; t < Lin; ++t) {
        float gn = act ? __half2float(__ldg(gp)) : 0.0f;   // row t+2 (padded)
        if (act) {
            const float* A = abuf[cur];
            float v;
            if (is_even) {
                v = lse2_(A[2 + l], A[1 + l]) + g0;        // blank: 2-term
            } else {
                const float a0 = A[2 + l];
                const float a1 = A[1 + l];
                const float a2 = allow2 ? A[l] : NEG2;
                const float m  = fmaxf(a0, fmaxf(a1, a2));
                const float sm = ex2f_(a0 - m) + ex2f_(a1 - m) + ex2f_(a2 - m);
                v = m + lg2f_(sm) + g0;                    // symbol: 3-term
            }
            abuf[cur ^ 1][2 + l] = v;
        }
        __syncthreads();
        cur ^= 1;
        g0 = g1; g1 = gn; gp += stride;
    }

    if (tid == 0) {
        const float* A = abuf[cur];
        const int idx = 2 * Lt;
        const float la2 = lse2_(A[2 + idx], A[1 + idx]);
        float loss = -la2 * LN2_F;
        if (!isfinite(loss) || loss > 0.5e30f) loss = 0.0f;   // zero_infinity
        g_partial[b] = loss / (float)Lt;
    }
}

// ---------------------------------------------------------------------------
// Phase 3: mean over batch -> out[0]
// ---------------------------------------------------------------------------
__global__ void ctc_phase3(float* __restrict__ out)
{
    const int lane = threadIdx.x;
    float v = g_partial[lane] + g_partial[lane + 32];
#pragma unroll
    for (int o = 16; o; o >>= 1) v += __shfl_xor_sync(0xffffffffu, v, o);
    if (lane == 0) out[0] = v / (float)B_DIM;
}

// ---------------------------------------------------------------------------
extern "C" void kernel_launch(void* const* d_in, const int* in_sizes, int n_in,
                              void* d_out, int out_size)
{
    const float* x    = (const float*)d_in[0];   // (T, B, V) float32
    const int*   tgt  = (const int*)d_in[1];     // (B, S) int32
    const int*   ilen = (const int*)d_in[2];     // (B,) int32
    const int*   tlen = (const int*)d_in[3];     // (B,) int32
    float*       out  = (float*)d_out;

    dim3 g1(B_DIM, T_DIM / 8);
    ctc_phase1<<<g1, 256>>>(x, tgt);
    ctc_phase2<<<B_DIM, NTH>>>(tgt, ilen, tlen);
    ctc_phase3<<<1, 32>>>(out);
}

// round 9
// speedup vs baseline: 3.0169x; 3.0169x over previous
#include <cuda_runtime.h>
#include <cuda_fp16.h>
#include <cstdint>
#include <math.h>

// Problem constants (CTCLoss_70961449664599): T=2048, B=64, V=512, S=256
#define T_DIM 2048
#define B_DIM 64
#define V_DIM 512
#define S_DIM 256
#define L_DIM (2 * S_DIM + 1)   // 513 extended positions
#define GP2   272               // padded row of halfs: cols 0..255 symbols, 256 blank
#define CHUNK 32                // time steps staged per cp.async group
#define TPAD  (T_DIM + 2 * CHUNK)  // row padding so prefetch never goes OOB
#define NEG2  (-1.0e30f)
#define LOG2E_F 1.4426950408889634f
#define LN2_F   0.6931471805599453f

// Scratch (allocation-free rule: __device__ globals). Layout: G[b][t][j],
// row stride GP2 halves; per-b column is contiguous for bulk staging.
// 16B alignment is REQUIRED for the cp.async.cg 16-byte copies below.
__device__ __align__(16) __half g_G[(size_t)B_DIM * TPAD * GP2];
__device__ float g_partial[B_DIM];

__device__ __forceinline__ float ex2f_(float x) {
    float y; asm("ex2.approx.f32 %0, %1;" : "=f"(y) : "f"(x)); return y;
}
__device__ __forceinline__ float lg2f_(float x) {
    float y; asm("lg2.approx.f32 %0, %1;" : "=f"(y) : "f"(x)); return y;
}
__device__ __forceinline__ float lse2_(float a, float b) {   // 2-term logaddexp2
    const float m = fmaxf(a, b);
    const float d = -fabsf(a - b);
    return m + lg2f_(1.0f + ex2f_(d));
}
__device__ __forceinline__ unsigned int smem_u32(const void* p) {
    unsigned int a;
    asm("{ .reg .u64 t; cvta.to.shared.u64 t, %1; cvt.u32.u64 %0, t; }"
        : "=r"(a) : "l"(p));
    return a;
}

// ---------------------------------------------------------------------------
// Phase 1: per (t,b) row -> log2-sum-exp; gathered log2-probs (fp16)
//   G[b][t][j] : j<256 -> symbol targets[b][j] (ext pos 2j+1), j=256 -> blank
// Grid: (B, T/8), block: 256 threads (8 warps, 1 warp per t-row)
// ---------------------------------------------------------------------------
__global__ __launch_bounds__(256) void ctc_phase1(
    const float* __restrict__ x, const int* __restrict__ targets)
{
    __shared__ float sh_row[8][V_DIM];
    __shared__ int   sh_tgt[S_DIM];

    const int b    = blockIdx.x;
    const int tid  = threadIdx.x;
    const int w    = tid >> 5;
    const int lane = tid & 31;

    sh_tgt[tid] = targets[b * S_DIM + tid];
    __syncthreads();

    const int t = blockIdx.y * 8 + w;
    const float4* row = (const float4*)(x + ((size_t)t * B_DIM + b) * V_DIM);

    float s = 0.0f;
    float4* shv = (float4*)sh_row[w];
#pragma unroll
    for (int k = 0; k < 4; k++) {
        float4 v = row[lane + 32 * k];
        shv[lane + 32 * k] = v;
        s += ex2f_(v.x * LOG2E_F) + ex2f_(v.y * LOG2E_F)
           + ex2f_(v.z * LOG2E_F) + ex2f_(v.w * LOG2E_F);
    }
#pragma unroll
    for (int o = 16; o; o >>= 1) s += __shfl_xor_sync(0xffffffffu, s, o);
    const float lse2v = lg2f_(s);

    __half* gout = g_G + ((size_t)b * TPAD + t) * GP2;
#pragma unroll
    for (int j = lane; j < 257; j += 32) {
        const int sym = (j < 256) ? sh_tgt[j] : 0;
        gout[j] = __float2half_rn(sh_row[w][sym] * LOG2E_F - lse2v);
    }
}

// ---------------------------------------------------------------------------
// Phase 2: alpha recursion (log2 domain), parity-segregated warps:
//   tid   0..256  -> even positions l = 2*tid   (blanks,  2-term LSE)
//   tid 257..287  -> idle (warp alignment)
//   tid 288..543  -> odd positions  l = 2*i+1   (symbols, 3-term LSE)
// G staged CHUNK steps at a time into double-buffered SMEM via cp.async;
// copy of chunk c+1 overlaps compute of chunk c. One __syncthreads per step.
// ---------------------------------------------------------------------------
#define NTH 544

__global__ __launch_bounds__(NTH) void ctc_phase2(
    const int* __restrict__ targets,
    const int* __restrict__ in_len,
    const int* __restrict__ tgt_len)
{
    __shared__ __align__(16) __half sgbuf[2][CHUNK * GP2];  // 34816 B
    __shared__ float abuf[2][L_DIM + 2];                    // [0],[1] NEG2 pads

    const int b   = blockIdx.x;
    const int tid = threadIdx.x;
    const int Lin = in_len[b];             // block-uniform
    const int Lt  = tgt_len[b];

    const bool is_even = (tid < 257);
    const bool act     = is_even | (tid >= 288);
    const int  i       = tid - 288;                      // odd pair index
    const int  l       = is_even ? (2 * tid) : (2 * i + 1);
    const int  j       = is_even ? 256 : i;              // column within a row

    bool allow2 = false;
    if (!is_even && act) {
        const int curt  = targets[b * S_DIM + i];
        const int prevt = (i > 0) ? targets[b * S_DIM + i - 1] : 0;
        allow2 = (curt != prevt);          // symbols >= 1, repeat check only
    }

    const __half* gbase = g_G + (size_t)b * TPAD * GP2;

    // t = 0 init: only positions 0,1 live
    if (tid < 2) { abuf[0][tid] = NEG2; abuf[1][tid] = NEG2; }
    if (act) abuf[0][2 + l] = (l < 2) ? __half2float(__ldg(gbase + j)) : NEG2;

    const unsigned int sdst0 = smem_u32(&sgbuf[0][0]);
    const unsigned int sdst1 = smem_u32(&sgbuf[1][0]);

    // stage chunk c (rows 1 + c*CHUNK .. +CHUNK-1) into sgbuf[c&1]
    auto stage = [&](int c) {
        const char* src = (const char*)(gbase + (size_t)(1 + c * CHUNK) * GP2);
        const unsigned int dst = (c & 1) ? sdst1 : sdst0;
#pragma unroll
        for (int k = 0; k < 2; k++) {
            const int e = tid + k * NTH;   // 2*544 = 1088 uint4 = whole chunk
            asm volatile("cp.async.cg.shared.global [%0], [%1], 16;"
                         :: "r"(dst + e * 16), "l"(src + (size_t)e * 16));
        }
        asm volatile("cp.async.commit_group;");
    };

    stage(0);
    const int nch = (Lin - 1 + CHUNK - 1) / CHUNK;

    int cur = 0;
    for (int c = 0; c < nch; c++) {
        stage(c + 1);                            // overlap with this chunk
        asm volatile("cp.async.wait_group 1;");  // chunk c resident
        __syncthreads();

        const __half* sb = sgbuf[c & 1];
        const int tmax = min(CHUNK, Lin - 1 - c * CHUNK);   // block-uniform
        for (int k = 0; k < tmax; k++) {
            if (act) {
                const float g = __half2float(sb[k * GP2 + j]);
                const float* A = abuf[cur];
                float v;
                if (is_even) {
                    v = lse2_(A[2 + l], A[1 + l]) + g;      // blank: 2-term
                } else {
                    const float a0 = A[2 + l];
                    const float a1 = A[1 + l];
                    const float a2 = allow2 ? A[l] : NEG2;
                    const float m  = fmaxf(a0, fmaxf(a1, a2));
                    const float sm = ex2f_(a0 - m) + ex2f_(a1 - m) + ex2f_(a2 - m);
                    v = m + lg2f_(sm) + g;                  // symbol: 3-term
                }
                abuf[cur ^ 1][2 + l] = v;
            }
            __syncthreads();
            cur ^= 1;
        }
    }

    if (tid == 0) {
        const float* A = abuf[cur];
        const int idx = 2 * Lt;
        const float la2 = lse2_(A[2 + idx], A[1 + idx]);
        float loss = -la2 * LN2_F;
        if (!isfinite(loss) || loss > 0.5e30f) loss = 0.0f;   // zero_infinity
        g_partial[b] = loss / (float)Lt;
    }
}

// ---------------------------------------------------------------------------
// Phase 3: mean over batch -> out[0]
// ---------------------------------------------------------------------------
__global__ void ctc_phase3(float* __restrict__ out)
{
    const int lane = threadIdx.x;
    float v = g_partial[lane] + g_partial[lane + 32];
#pragma unroll
    for (int o = 16; o; o >>= 1) v += __shfl_xor_sync(0xffffffffu, v, o);
    if (lane == 0) out[0] = v / (float)B_DIM;
}

// ---------------------------------------------------------------------------
extern "C" void kernel_launch(void* const* d_in, const int* in_sizes, int n_in,
                              void* d_out, int out_size)
{
    const float* x    = (const float*)d_in[0];   // (T, B, V) float32
    const int*   tgt  = (const int*)d_in[1];     // (B, S) int32
    const int*   ilen = (const int*)d_in[2];     // (B,) int32
    const int*   tlen = (const int*)d_in[3];     // (B,) int32
    float*       out  = (float*)d_out;

    dim3 g1(B_DIM, T_DIM / 8);
    ctc_phase1<<<g1, 256>>>(x, tgt);
    ctc_phase2<<<B_DIM, NTH>>>(tgt, ilen, tlen);
    ctc_phase3<<<1, 32>>>(out);
}